// round 12
// baseline (speedup 1.0000x reference)
#include <cuda_runtime.h>
#include <cuda_bf16.h>
#include <cuda_fp16.h>
#include <cstdint>

#define NROWS 8192
#define KDIM  256
#define CDIM  256      // H*O
#define NHEAD 4
#define ODIM  64
#define NB    512      // concat B cols: [weight | proj_w^T]
#define MAXE  1024     // max edges per row (mean ~410, 30-sigma safe)
#define LN256 5.5451774444795624f

// ---------------- device scratch (no allocation allowed) ----------------
__device__ __nv_bfloat16 g_Ah[NROWS * KDIM];   // 4 MB  A hi (row-major)
__device__ __nv_bfloat16 g_Al[NROWS * KDIM];   // 4 MB  A lo
__device__ __nv_bfloat16 g_Bht[NB * KDIM];     // 256 KB B hi, n-major [n][k]
__device__ __nv_bfloat16 g_Blt[NB * KDIM];     // 256 KB B lo
__device__ __half2 g_supp_h[NROWS * (CDIM/2)]; // 4 MB (fp16, for aggregation)
__device__ float4  g_f1v[NROWS];               // 128 KB (4 heads packed)
__device__ float4  g_f2v[NROWS];               // 128 KB
__device__ int     g_maxf1i[NHEAD];            // global per-head max of f1 (bits)

// ---------------- kernel 0a: split A into bf16 hi/lo ----------------
__global__ void split_a_kernel(const float* __restrict__ inputs) {
    int idx = blockIdx.x * 256 + threadIdx.x;      // 0 .. 2M/4-1
    float4 v = *(const float4*)&inputs[(size_t)idx * 4];
    __nv_bfloat16 h0 = __float2bfloat16_rn(v.x);
    __nv_bfloat16 h1 = __float2bfloat16_rn(v.y);
    __nv_bfloat16 h2 = __float2bfloat16_rn(v.z);
    __nv_bfloat16 h3 = __float2bfloat16_rn(v.w);
    __nv_bfloat16 l0 = __float2bfloat16_rn(v.x - __bfloat162float(h0));
    __nv_bfloat16 l1 = __float2bfloat16_rn(v.y - __bfloat162float(h1));
    __nv_bfloat16 l2 = __float2bfloat16_rn(v.z - __bfloat162float(h2));
    __nv_bfloat16 l3 = __float2bfloat16_rn(v.w - __bfloat162float(h3));
    __nv_bfloat162 hp0 = {h0, h1}, hp1 = {h2, h3};
    __nv_bfloat162 lp0 = {l0, l1}, lp1 = {l2, l3};
    uint2 hw, lw;
    hw.x = *(unsigned*)&hp0; hw.y = *(unsigned*)&hp1;
    lw.x = *(unsigned*)&lp0; lw.y = *(unsigned*)&lp1;
    *(uint2*)&g_Ah[(size_t)idx * 4] = hw;
    *(uint2*)&g_Al[(size_t)idx * 4] = lw;
}

// ---------------- kernel 0b: pack B^T = [weight | proj_w^T] hi/lo, n-major ---
__global__ void pack_bt_kernel(const float* __restrict__ weight,
                               const float* __restrict__ proj_w) {
    int n = blockIdx.x;            // 0..511
    int k = threadIdx.x;           // 0..255
    if (n == 0 && k < NHEAD) g_maxf1i[k] = 0;
    float v = (n < 256) ? weight[k * 256 + n]
                        : proj_w[(n - 256) * 256 + k];
    __nv_bfloat16 h = __float2bfloat16_rn(v);
    __nv_bfloat16 l = __float2bfloat16_rn(v - __bfloat162float(h));
    g_Bht[(size_t)n * KDIM + k] = h;
    g_Blt[(size_t)n * KDIM + k] = l;
}

// ---------------- mma.sync wrapper ----------------
__device__ __forceinline__ void mma16816(float* d, const unsigned* a, const unsigned* b) {
    asm volatile(
        "mma.sync.aligned.m16n8k16.row.col.f32.bf16.bf16.f32 "
        "{%0,%1,%2,%3}, {%4,%5,%6,%7}, {%8,%9}, {%0,%1,%2,%3};\n"
        : "+f"(d[0]), "+f"(d[1]), "+f"(d[2]), "+f"(d[3])
        : "r"(a[0]), "r"(a[1]), "r"(a[2]), "r"(a[3]), "r"(b[0]), "r"(b[1]));
}

// ---------------- kernel 1: tensor-core GEMM [8192,256]x[256,512] ----------
// (verbatim R11 — proven ~40us with prep)
__global__ void __launch_bounds__(256)
gemm_kernel(const float* __restrict__ wu,
            const float* __restrict__ wv,
            const float* __restrict__ bias,
            const float* __restrict__ proj_b,
            float* __restrict__ out) {
    __shared__ __nv_bfloat16 As[128][40];   // [row][k: 0-15 hi, 16-31 lo] pad->40
    __shared__ __nv_bfloat16 Bs[64][40];    // [n][k: 0-15 hi, 16-31 lo]
    __shared__ float s_u[2][128];
    __shared__ float s_v[2][128];
    __shared__ float s_mx[4];

    const int tid   = threadIdx.x;
    const int lane  = tid & 31;
    const int warp  = tid >> 5;
    const int warpM = warp >> 1;     // 0..3
    const int warpN = warp & 1;      // 0..1
    const int wr = warpM * 32;
    const int wn = warpN * 32;
    const int r = lane >> 2;         // 0..7
    const int t = lane & 3;          // 0..3
    const int row0 = blockIdx.y * 128;
    const int col0 = blockIdx.x * 64;

    float acc[2][4][4] = {};

    const int arow  = tid >> 1;          // 0..127
    const int ahalf = tid & 1;
    const int bn    = (tid & 127) >> 1;  // 0..63
    const int bhalf = tid & 1;
    const int bsel  = tid >> 7;          // 0: hi, 1: lo

    for (int kc = 0; kc < 16; kc++) {
        const int k0 = kc * 16;
        __syncthreads();
        {
            uint4 hv = *(const uint4*)&g_Ah[(size_t)(row0 + arow) * KDIM + k0 + ahalf * 8];
            uint4 lv = *(const uint4*)&g_Al[(size_t)(row0 + arow) * KDIM + k0 + ahalf * 8];
            *(uint4*)&As[arow][ahalf * 8]      = hv;
            *(uint4*)&As[arow][16 + ahalf * 8] = lv;
        }
        {
            const __nv_bfloat16* src = bsel ? g_Blt : g_Bht;
            uint4 v = *(const uint4*)&src[(size_t)(col0 + bn) * KDIM + k0 + bhalf * 8];
            *(uint4*)&Bs[bn][bsel * 16 + bhalf * 8] = v;
        }
        __syncthreads();

        unsigned aH[2][4], aL[2][4], bH[4][2], bL[4][2];
        #pragma unroll
        for (int mt = 0; mt < 2; mt++) {
            int rr = wr + mt * 16 + r;
            aH[mt][0] = *(const unsigned*)&As[rr][2 * t];
            aH[mt][1] = *(const unsigned*)&As[rr + 8][2 * t];
            aH[mt][2] = *(const unsigned*)&As[rr][2 * t + 8];
            aH[mt][3] = *(const unsigned*)&As[rr + 8][2 * t + 8];
            aL[mt][0] = *(const unsigned*)&As[rr][16 + 2 * t];
            aL[mt][1] = *(const unsigned*)&As[rr + 8][16 + 2 * t];
            aL[mt][2] = *(const unsigned*)&As[rr][16 + 2 * t + 8];
            aL[mt][3] = *(const unsigned*)&As[rr + 8][16 + 2 * t + 8];
        }
        #pragma unroll
        for (int nt = 0; nt < 4; nt++) {
            int cc = wn + nt * 8 + r;
            bH[nt][0] = *(const unsigned*)&Bs[cc][2 * t];
            bH[nt][1] = *(const unsigned*)&Bs[cc][2 * t + 8];
            bL[nt][0] = *(const unsigned*)&Bs[cc][16 + 2 * t];
            bL[nt][1] = *(const unsigned*)&Bs[cc][16 + 2 * t + 8];
        }
        #pragma unroll
        for (int mt = 0; mt < 2; mt++)
            #pragma unroll
            for (int nt = 0; nt < 4; nt++) {
                mma16816(acc[mt][nt], aH[mt], bH[nt]);
                mma16816(acc[mt][nt], aL[mt], bH[nt]);
                mma16816(acc[mt][nt], aH[mt], bL[nt]);
            }
    }

    if (col0 < 256) {
        const int h = col0 >> 6;
        float u2[2][2] = {}, v2[2][2] = {};
        #pragma unroll
        for (int mt = 0; mt < 2; mt++) {
            int rowa = row0 + wr + mt * 16 + r;
            #pragma unroll
            for (int nt = 0; nt < 4; nt++) {
                int o = wn + nt * 8 + 2 * t;
                float wu0 = wu[h * 64 + o], wu1 = wu[h * 64 + o + 1];
                float wv0 = wv[h * 64 + o], wv1 = wv[h * 64 + o + 1];
                float* A4 = acc[mt][nt];
                g_supp_h[(size_t)rowa * 128 + ((col0 + o) >> 1)] =
                    __float22half2_rn(make_float2(A4[0], A4[1]));
                g_supp_h[(size_t)(rowa + 8) * 128 + ((col0 + o) >> 1)] =
                    __float22half2_rn(make_float2(A4[2], A4[3]));
                u2[mt][0] += A4[0] * wu0 + A4[1] * wu1;
                u2[mt][1] += A4[2] * wu0 + A4[3] * wu1;
                v2[mt][0] += A4[0] * wv0 + A4[1] * wv1;
                v2[mt][1] += A4[2] * wv0 + A4[3] * wv1;
            }
        }
        #pragma unroll
        for (int off = 1; off <= 2; off <<= 1)
            #pragma unroll
            for (int mt = 0; mt < 2; mt++) {
                u2[mt][0] += __shfl_xor_sync(0xFFFFFFFFu, u2[mt][0], off);
                u2[mt][1] += __shfl_xor_sync(0xFFFFFFFFu, u2[mt][1], off);
                v2[mt][0] += __shfl_xor_sync(0xFFFFFFFFu, v2[mt][0], off);
                v2[mt][1] += __shfl_xor_sync(0xFFFFFFFFu, v2[mt][1], off);
            }
        if (t == 0) {
            #pragma unroll
            for (int mt = 0; mt < 2; mt++) {
                int lr = wr + mt * 16 + r;
                s_u[warpN][lr]     = u2[mt][0];
                s_u[warpN][lr + 8] = u2[mt][1];
                s_v[warpN][lr]     = v2[mt][0];
                s_v[warpN][lr + 8] = v2[mt][1];
            }
        }
        __syncthreads();
        if (tid < 128) {
            float u = s_u[0][tid] + s_u[1][tid];
            float v = s_v[0][tid] + s_v[1][tid];
            ((float*)&g_f1v[row0 + tid])[h] = u;
            ((float*)&g_f2v[row0 + tid])[h] = v;
            float m = u;
            #pragma unroll
            for (int off = 16; off; off >>= 1)
                m = fmaxf(m, __shfl_xor_sync(0xFFFFFFFFu, m, off));
            if (lane == 0) s_mx[warp] = m;
        }
        __syncthreads();
        if (tid == 0) {
            float m = fmaxf(fmaxf(s_mx[0], s_mx[1]), fmaxf(s_mx[2], s_mx[3]));
            if (m > 0.f) atomicMax(&g_maxf1i[h], __float_as_int(m));
        }
    } else {
        #pragma unroll
        for (int mt = 0; mt < 2; mt++) {
            int rowa = row0 + wr + mt * 16 + r;
            #pragma unroll
            for (int nt = 0; nt < 4; nt++) {
                int cc = col0 - 256 + wn + nt * 8 + 2 * t;
                float b0 = bias[cc] + proj_b[cc];
                float b1 = bias[cc + 1] + proj_b[cc + 1];
                float* A4 = acc[mt][nt];
                *(float2*)&out[(size_t)rowa * CDIM + cc] =
                    make_float2(A4[0] + b0, A4[1] + b1);
                *(float2*)&out[(size_t)(rowa + 8) * CDIM + cc] =
                    make_float2(A4[2] + b0, A4[3] + b1);
            }
        }
    }
}

// ---------------- kernel 2: per-row sparse softmax + aggregation ----------------
// Phase 1 keeps SoA s_cols (conflict-free). Phase 2 packs 16B records
// {j, 0, p01, p23} via clean STS.128. Phase 3 does ONE broadcast LDS.128/edge.
__global__ void __launch_bounds__(256)
attn_kernel(const float* __restrict__ adj, float* __restrict__ out) {
    __shared__ int     s_cols[MAXE];         // 4 KB (phase-1 writes, phase-2 reads)
    __shared__ uint4   s_rec[MAXE];          // 16 KB edge records
    __shared__ float   s_part[8][32][9];     // [group][thread][8ch + pad]
    __shared__ float   s_red[NHEAD][8];
    __shared__ float   s_inv[NHEAD];
    __shared__ int     s_cnt;

    const int i = blockIdx.x;
    const int tid = threadIdx.x;
    const int lane = tid & 31;
    const int warp = tid >> 5;

    if (tid == 0) s_cnt = 0;
    __syncthreads();

    // ---- phase 1: gather nonzero columns (float4 reads, ballot compaction) ----
    const float4* arow = (const float4*)(adj + (size_t)i * NROWS);
    const unsigned ltmask = (1u << lane) - 1u;
    #pragma unroll
    for (int it = 0; it < 8; it++) {
        int idx4 = it * 256 + tid;
        float4 v = arow[idx4];
        bool n0 = v.x != 0.f, n1 = v.y != 0.f, n2 = v.z != 0.f, n3 = v.w != 0.f;
        unsigned b0 = __ballot_sync(0xFFFFFFFFu, n0);
        unsigned b1 = __ballot_sync(0xFFFFFFFFu, n1);
        unsigned b2 = __ballot_sync(0xFFFFFFFFu, n2);
        unsigned b3 = __ballot_sync(0xFFFFFFFFu, n3);
        int tot = __popc(b0) + __popc(b1) + __popc(b2) + __popc(b3);
        int base = 0;
        if (lane == 0 && tot) base = atomicAdd(&s_cnt, tot);
        base = __shfl_sync(0xFFFFFFFFu, base, 0);
        int c0 = idx4 * 4;
        int p0 = base + __popc(b0 & ltmask);
        int p1 = base + __popc(b0) + __popc(b1 & ltmask);
        int p2 = base + __popc(b0) + __popc(b1) + __popc(b2 & ltmask);
        int p3 = base + __popc(b0) + __popc(b1) + __popc(b2) + __popc(b3 & ltmask);
        if (n0 && p0 < MAXE) s_cols[p0] = c0;
        if (n1 && p1 < MAXE) s_cols[p1] = c0 + 1;
        if (n2 && p2 < MAXE) s_cols[p2] = c0 + 2;
        if (n3 && p3 < MAXE) s_cols[p3] = c0 + 3;
    }
    __syncthreads();
    const int cnt = min(s_cnt, MAXE);

    // ---- phase 2: lrelu + scaled exp -> 16B records {j,0,p01,p23} ----
    const float4 f2h = g_f2v[i];
    float Cx, Cy, Cz, Cw;
    {
        float gx = __int_as_float(g_maxf1i[0]);
        float gy = __int_as_float(g_maxf1i[1]);
        float gz = __int_as_float(g_maxf1i[2]);
        float gw = __int_as_float(g_maxf1i[3]);
        float ax = gx + f2h.x; ax = (ax > 0.f) ? ax : 0.2f * ax;
        float ay = gy + f2h.y; ay = (ay > 0.f) ? ay : 0.2f * ay;
        float az = gz + f2h.z; az = (az > 0.f) ? az : 0.2f * az;
        float aw = gw + f2h.w; aw = (aw > 0.f) ? aw : 0.2f * aw;
        Cx = LN256 - ax; Cy = LN256 - ay; Cz = LN256 - az; Cw = LN256 - aw;
    }
    float4 sm = make_float4(0.f, 0.f, 0.f, 0.f);
    for (int e = tid; e < cnt; e += 256) {
        int j = s_cols[e];
        float4 f1 = __ldg(&g_f1v[j]);
        float sx = f1.x + f2h.x; sx = (sx > 0.f) ? sx : 0.2f * sx;
        float sy = f1.y + f2h.y; sy = (sy > 0.f) ? sy : 0.2f * sy;
        float sz = f1.z + f2h.z; sz = (sz > 0.f) ? sz : 0.2f * sz;
        float sw = f1.w + f2h.w; sw = (sw > 0.f) ? sw : 0.2f * sw;
        float px = __expf(sx + Cx), py = __expf(sy + Cy);
        float pz = __expf(sz + Cz), pw = __expf(sw + Cw);
        __half2 h01 = __float22half2_rn(make_float2(px, py));
        __half2 h23 = __float22half2_rn(make_float2(pz, pw));
        uint4 rec;
        rec.x = (unsigned)j;
        rec.y = 0u;
        rec.z = *(unsigned*)&h01;
        rec.w = *(unsigned*)&h23;
        s_rec[e] = rec;
        sm.x += px; sm.y += py; sm.z += pz; sm.w += pw;
    }
    #pragma unroll
    for (int off = 16; off; off >>= 1) {
        sm.x += __shfl_xor_sync(0xFFFFFFFFu, sm.x, off);
        sm.y += __shfl_xor_sync(0xFFFFFFFFu, sm.y, off);
        sm.z += __shfl_xor_sync(0xFFFFFFFFu, sm.z, off);
        sm.w += __shfl_xor_sync(0xFFFFFFFFu, sm.w, off);
    }
    if (lane == 0) {
        s_red[0][warp] = sm.x; s_red[1][warp] = sm.y;
        s_red[2][warp] = sm.z; s_red[3][warp] = sm.w;
    }
    __syncthreads();
    if (tid < NHEAD) {
        float D = 0.f;
        #pragma unroll
        for (int w = 0; w < 8; w++) D += s_red[tid][w];
        s_inv[tid] = (D > 0.f) ? (1.0f / D) : 0.f;
    }
    __syncthreads();

    // ---- phase 3: 8 edge-groups x 32 threads, 1 broadcast LDS.128 per edge ----
    const int g = warp;               // edge phase 0..7
    const int t = lane;               // channels [8t, 8t+8)
    const int hsel2 = (t >> 4) & 1;   // head bit1: rec.z vs rec.w
    const int hsel1 = (t >> 3) & 1;   // head bit0: low vs high half
    const char* supb = (const char*)g_supp_h + t * 16;   // hoisted lane offset

    float facc[8] = {};
    int e = g;
    for (; e + 56 < cnt; e += 64) {
        __half2 h0 = __float2half2_rn(0.f), h1 = h0, h2 = h0, h3 = h0;
        #pragma unroll
        for (int u = 0; u < 8; u++) {
            uint4 rec = s_rec[e + u * 8];
            unsigned praw = hsel2 ? rec.w : rec.z;
            __half2 pv = *(__half2*)&praw;
            __half2 ph = hsel1 ? __high2half2(pv) : __low2half2(pv);
            unsigned off = rec.x << 9;          // j * 512 bytes
            uint4 v = *(const uint4*)(supb + off);
            h0 = __hfma2(ph, *(__half2*)&v.x, h0);
            h1 = __hfma2(ph, *(__half2*)&v.y, h1);
            h2 = __hfma2(ph, *(__half2*)&v.z, h2);
            h3 = __hfma2(ph, *(__half2*)&v.w, h3);
        }
        float2 f0 = __half22float2(h0), f1 = __half22float2(h1);
        float2 f2 = __half22float2(h2), f3 = __half22float2(h3);
        facc[0] += f0.x; facc[1] += f0.y; facc[2] += f1.x; facc[3] += f1.y;
        facc[4] += f2.x; facc[5] += f2.y; facc[6] += f3.x; facc[7] += f3.y;
    }
    for (; e < cnt; e += 8) {
        uint4 rec = s_rec[e];
        unsigned praw = hsel2 ? rec.w : rec.z;
        __half2 pv = *(__half2*)&praw;
        float p = __half2float(hsel1 ? __high2half(pv) : __low2half(pv));
        unsigned off = rec.x << 9;
        uint4 v = *(const uint4*)(supb + off);
        float2 f0 = __half22float2(*(__half2*)&v.x);
        float2 f1 = __half22float2(*(__half2*)&v.y);
        float2 f2 = __half22float2(*(__half2*)&v.z);
        float2 f3 = __half22float2(*(__half2*)&v.w);
        facc[0] += p * f0.x; facc[1] += p * f0.y;
        facc[2] += p * f1.x; facc[3] += p * f1.y;
        facc[4] += p * f2.x; facc[5] += p * f2.y;
        facc[6] += p * f3.x; facc[7] += p * f3.y;
    }
    #pragma unroll
    for (int k = 0; k < 8; k++) s_part[g][t][k] = facc[k];
    __syncthreads();

    // ---- phase 4: combine 8 groups, normalize, add base, store ----
    if (tid < 32) {
        const float inv = s_inv[tid >> 3];
        float r[8] = {};
        #pragma unroll
        for (int gg = 0; gg < 8; gg++)
            #pragma unroll
            for (int k = 0; k < 8; k++)
                r[k] += s_part[gg][tid][k];
        float4* o = (float4*)(out + (size_t)i * CDIM);
        float4 b0 = o[tid * 2];
        float4 b1 = o[tid * 2 + 1];
        b0.x += r[0] * inv; b0.y += r[1] * inv; b0.z += r[2] * inv; b0.w += r[3] * inv;
        b1.x += r[4] * inv; b1.y += r[5] * inv; b1.z += r[6] * inv; b1.w += r[7] * inv;
        o[tid * 2]     = b0;
        o[tid * 2 + 1] = b1;
    }
}

// ---------------- launch ----------------
extern "C" void kernel_launch(void* const* d_in, const int* in_sizes, int n_in,
                              void* d_out, int out_size) {
    const float* inputs  = (const float*)d_in[0];  // [8192,256]
    const float* adj     = (const float*)d_in[1];  // [8192,8192]
    const float* weight  = (const float*)d_in[2];  // [256,256]
    const float* wu      = (const float*)d_in[3];  // [4,64,1]
    const float* wv      = (const float*)d_in[4];  // [4,64,1]
    const float* bias    = (const float*)d_in[5];  // [1,256]
    const float* proj_w  = (const float*)d_in[6];  // [256,256]
    const float* proj_b  = (const float*)d_in[7];  // [256]
    float* out = (float*)d_out;                    // [8192,256]

    split_a_kernel<<<(NROWS * KDIM / 4) / 256, 256>>>(inputs);
    pack_bt_kernel<<<NB, KDIM>>>(weight, proj_w);

    dim3 ggrid(NB / 64, NROWS / 128);
    gemm_kernel<<<ggrid, 256>>>(wu, wv, bias, proj_b, out);

    attn_kernel<<<NROWS, 256>>>(adj, out);
}

// round 13
// speedup vs baseline: 1.1197x; 1.1197x over previous
#include <cuda_runtime.h>
#include <cuda_bf16.h>
#include <cuda_fp16.h>
#include <cstdint>

#define NROWS 8192
#define KDIM  256
#define CDIM  256      // H*O
#define NHEAD 4
#define ODIM  64
#define NB    512      // concat B cols: [weight | proj_w^T]
#define MAXE  1024     // max edges per row (mean ~410, 30-sigma safe)
#define LN256 5.5451774444795624f

// ---------------- device scratch (no allocation allowed) ----------------
__device__ __nv_bfloat16 g_Ah[NROWS * KDIM];   // 4 MB  A hi (row-major)
__device__ __nv_bfloat16 g_Al[NROWS * KDIM];   // 4 MB  A lo
__device__ __nv_bfloat16 g_Bht[NB * KDIM];     // 256 KB B hi, n-major [n][k]
__device__ __nv_bfloat16 g_Blt[NB * KDIM];     // 256 KB B lo
__device__ __half2 g_supp_h[NROWS * (CDIM/2)]; // 4 MB (fp16, for aggregation)
__device__ float4  g_f1v[NROWS];               // 128 KB (4 heads packed)
__device__ float4  g_f2v[NROWS];               // 128 KB
__device__ int     g_maxf1i[NHEAD];            // global per-head max of f1 (bits)

// ---------------- kernel 0a: split A into bf16 hi/lo ----------------
__global__ void split_a_kernel(const float* __restrict__ inputs) {
    int idx = blockIdx.x * 256 + threadIdx.x;      // 0 .. 2M/4-1
    float4 v = *(const float4*)&inputs[(size_t)idx * 4];
    __nv_bfloat16 h0 = __float2bfloat16_rn(v.x);
    __nv_bfloat16 h1 = __float2bfloat16_rn(v.y);
    __nv_bfloat16 h2 = __float2bfloat16_rn(v.z);
    __nv_bfloat16 h3 = __float2bfloat16_rn(v.w);
    __nv_bfloat16 l0 = __float2bfloat16_rn(v.x - __bfloat162float(h0));
    __nv_bfloat16 l1 = __float2bfloat16_rn(v.y - __bfloat162float(h1));
    __nv_bfloat16 l2 = __float2bfloat16_rn(v.z - __bfloat162float(h2));
    __nv_bfloat16 l3 = __float2bfloat16_rn(v.w - __bfloat162float(h3));
    __nv_bfloat162 hp0 = {h0, h1}, hp1 = {h2, h3};
    __nv_bfloat162 lp0 = {l0, l1}, lp1 = {l2, l3};
    uint2 hw, lw;
    hw.x = *(unsigned*)&hp0; hw.y = *(unsigned*)&hp1;
    lw.x = *(unsigned*)&lp0; lw.y = *(unsigned*)&lp1;
    *(uint2*)&g_Ah[(size_t)idx * 4] = hw;
    *(uint2*)&g_Al[(size_t)idx * 4] = lw;
}

// ---------------- kernel 0b: pack B^T = [weight | proj_w^T] hi/lo, n-major ---
__global__ void pack_bt_kernel(const float* __restrict__ weight,
                               const float* __restrict__ proj_w) {
    int n = blockIdx.x;            // 0..511
    int k = threadIdx.x;           // 0..255
    if (n == 0 && k < NHEAD) g_maxf1i[k] = 0;
    float v = (n < 256) ? weight[k * 256 + n]
                        : proj_w[(n - 256) * 256 + k];
    __nv_bfloat16 h = __float2bfloat16_rn(v);
    __nv_bfloat16 l = __float2bfloat16_rn(v - __bfloat162float(h));
    g_Bht[(size_t)n * KDIM + k] = h;
    g_Blt[(size_t)n * KDIM + k] = l;
}

// ---------------- mma.sync + cp.async wrappers ----------------
__device__ __forceinline__ void mma16816(float* d, const unsigned* a, const unsigned* b) {
    asm volatile(
        "mma.sync.aligned.m16n8k16.row.col.f32.bf16.bf16.f32 "
        "{%0,%1,%2,%3}, {%4,%5,%6,%7}, {%8,%9}, {%0,%1,%2,%3};\n"
        : "+f"(d[0]), "+f"(d[1]), "+f"(d[2]), "+f"(d[3])
        : "r"(a[0]), "r"(a[1]), "r"(a[2]), "r"(a[3]), "r"(b[0]), "r"(b[1]));
}
__device__ __forceinline__ void cpasync16(uint32_t s, const void* g) {
    asm volatile("cp.async.ca.shared.global [%0], [%1], 16;\n" :: "r"(s), "l"(g));
}
__device__ __forceinline__ uint32_t s2u(const void* p) {
    return (uint32_t)__cvta_generic_to_shared(p);
}

// ---------------- kernel 1: tensor-core GEMM with cp.async pipeline ----------
// split-bf16 3-product emulation; block tile 128x64; 2-stage smem pipeline.
__global__ void __launch_bounds__(256)
gemm_kernel(const float* __restrict__ wu,
            const float* __restrict__ wv,
            const float* __restrict__ bias,
            const float* __restrict__ proj_b,
            float* __restrict__ out) {
    __shared__ __nv_bfloat16 As[2][128][40];   // [buf][row][k: 0-15 hi,16-31 lo]
    __shared__ __nv_bfloat16 Bs[2][64][40];
    __shared__ float s_u[2][128];
    __shared__ float s_v[2][128];
    __shared__ float s_mx[4];

    const int tid   = threadIdx.x;
    const int lane  = tid & 31;
    const int warp  = tid >> 5;
    const int warpM = warp >> 1;     // 0..3
    const int warpN = warp & 1;      // 0..1
    const int wr = warpM * 32;
    const int wn = warpN * 32;
    const int r = lane >> 2;         // 0..7
    const int t = lane & 3;          // 0..3
    const int row0 = blockIdx.y * 128;
    const int col0 = blockIdx.x * 64;

    float acc[2][4][4] = {};

    const int arow  = tid >> 1;          // 0..127
    const int ahalf = tid & 1;
    const int bn    = (tid & 127) >> 1;  // 0..63
    const int bhalf = tid & 1;
    const int bsel  = tid >> 7;          // 0: hi, 1: lo
    const __nv_bfloat16* bsrc = bsel ? g_Blt : g_Bht;

    // per-thread staging addresses (smem side fixed per buffer)
    uint32_t sA_h[2], sA_l[2], sB[2];
    #pragma unroll
    for (int b = 0; b < 2; b++) {
        sA_h[b] = s2u(&As[b][arow][ahalf * 8]);
        sA_l[b] = s2u(&As[b][arow][16 + ahalf * 8]);
        sB[b]   = s2u(&Bs[b][bn][bsel * 16 + bhalf * 8]);
    }
    const __nv_bfloat16* gA_h = &g_Ah[(size_t)(row0 + arow) * KDIM + ahalf * 8];
    const __nv_bfloat16* gA_l = &g_Al[(size_t)(row0 + arow) * KDIM + ahalf * 8];
    const __nv_bfloat16* gB   = &bsrc[(size_t)(col0 + bn) * KDIM + bhalf * 8];

    // prologue: stage chunk 0 into buf 0
    cpasync16(sA_h[0], gA_h);
    cpasync16(sA_l[0], gA_l);
    cpasync16(sB[0],   gB);
    asm volatile("cp.async.commit_group;\n");

    for (int kc = 0; kc < 16; kc++) {
        const int cur = kc & 1;
        if (kc + 1 < 16) {
            const int nxt = cur ^ 1;
            const int k1 = (kc + 1) * 16;
            cpasync16(sA_h[nxt], gA_h + k1);
            cpasync16(sA_l[nxt], gA_l + k1);
            cpasync16(sB[nxt],   gB + k1);
            asm volatile("cp.async.commit_group;\n");
            asm volatile("cp.async.wait_group 1;\n");
        } else {
            asm volatile("cp.async.wait_group 0;\n");
        }
        __syncthreads();

        unsigned aH[2][4], aL[2][4], bH[4][2], bL[4][2];
        #pragma unroll
        for (int mt = 0; mt < 2; mt++) {
            int rr = wr + mt * 16 + r;
            aH[mt][0] = *(const unsigned*)&As[cur][rr][2 * t];
            aH[mt][1] = *(const unsigned*)&As[cur][rr + 8][2 * t];
            aH[mt][2] = *(const unsigned*)&As[cur][rr][2 * t + 8];
            aH[mt][3] = *(const unsigned*)&As[cur][rr + 8][2 * t + 8];
            aL[mt][0] = *(const unsigned*)&As[cur][rr][16 + 2 * t];
            aL[mt][1] = *(const unsigned*)&As[cur][rr + 8][16 + 2 * t];
            aL[mt][2] = *(const unsigned*)&As[cur][rr][16 + 2 * t + 8];
            aL[mt][3] = *(const unsigned*)&As[cur][rr + 8][16 + 2 * t + 8];
        }
        #pragma unroll
        for (int nt = 0; nt < 4; nt++) {
            int cc = wn + nt * 8 + r;
            bH[nt][0] = *(const unsigned*)&Bs[cur][cc][2 * t];
            bH[nt][1] = *(const unsigned*)&Bs[cur][cc][2 * t + 8];
            bL[nt][0] = *(const unsigned*)&Bs[cur][cc][16 + 2 * t];
            bL[nt][1] = *(const unsigned*)&Bs[cur][cc][16 + 2 * t + 8];
        }
        #pragma unroll
        for (int mt = 0; mt < 2; mt++)
            #pragma unroll
            for (int nt = 0; nt < 4; nt++) {
                mma16816(acc[mt][nt], aH[mt], bH[nt]);
                mma16816(acc[mt][nt], aL[mt], bH[nt]);
                mma16816(acc[mt][nt], aH[mt], bL[nt]);
            }
        __syncthreads();
    }

    // ---- epilogue (unchanged from R11) ----
    if (col0 < 256) {
        const int h = col0 >> 6;
        float u2[2][2] = {}, v2[2][2] = {};
        #pragma unroll
        for (int mt = 0; mt < 2; mt++) {
            int rowa = row0 + wr + mt * 16 + r;
            #pragma unroll
            for (int nt = 0; nt < 4; nt++) {
                int o = wn + nt * 8 + 2 * t;
                float wu0 = wu[h * 64 + o], wu1 = wu[h * 64 + o + 1];
                float wv0 = wv[h * 64 + o], wv1 = wv[h * 64 + o + 1];
                float* A4 = acc[mt][nt];
                g_supp_h[(size_t)rowa * 128 + ((col0 + o) >> 1)] =
                    __float22half2_rn(make_float2(A4[0], A4[1]));
                g_supp_h[(size_t)(rowa + 8) * 128 + ((col0 + o) >> 1)] =
                    __float22half2_rn(make_float2(A4[2], A4[3]));
                u2[mt][0] += A4[0] * wu0 + A4[1] * wu1;
                u2[mt][1] += A4[2] * wu0 + A4[3] * wu1;
                v2[mt][0] += A4[0] * wv0 + A4[1] * wv1;
                v2[mt][1] += A4[2] * wv0 + A4[3] * wv1;
            }
        }
        #pragma unroll
        for (int off = 1; off <= 2; off <<= 1)
            #pragma unroll
            for (int mt = 0; mt < 2; mt++) {
                u2[mt][0] += __shfl_xor_sync(0xFFFFFFFFu, u2[mt][0], off);
                u2[mt][1] += __shfl_xor_sync(0xFFFFFFFFu, u2[mt][1], off);
                v2[mt][0] += __shfl_xor_sync(0xFFFFFFFFu, v2[mt][0], off);
                v2[mt][1] += __shfl_xor_sync(0xFFFFFFFFu, v2[mt][1], off);
            }
        if (t == 0) {
            #pragma unroll
            for (int mt = 0; mt < 2; mt++) {
                int lr = wr + mt * 16 + r;
                s_u[warpN][lr]     = u2[mt][0];
                s_u[warpN][lr + 8] = u2[mt][1];
                s_v[warpN][lr]     = v2[mt][0];
                s_v[warpN][lr + 8] = v2[mt][1];
            }
        }
        __syncthreads();
        if (tid < 128) {
            float u = s_u[0][tid] + s_u[1][tid];
            float v = s_v[0][tid] + s_v[1][tid];
            ((float*)&g_f1v[row0 + tid])[h] = u;
            ((float*)&g_f2v[row0 + tid])[h] = v;
            float m = u;
            #pragma unroll
            for (int off = 16; off; off >>= 1)
                m = fmaxf(m, __shfl_xor_sync(0xFFFFFFFFu, m, off));
            if (lane == 0) s_mx[warp] = m;
        }
        __syncthreads();
        if (tid == 0) {
            float m = fmaxf(fmaxf(s_mx[0], s_mx[1]), fmaxf(s_mx[2], s_mx[3]));
            if (m > 0.f) atomicMax(&g_maxf1i[h], __float_as_int(m));
        }
    } else {
        #pragma unroll
        for (int mt = 0; mt < 2; mt++) {
            int rowa = row0 + wr + mt * 16 + r;
            #pragma unroll
            for (int nt = 0; nt < 4; nt++) {
                int cc = col0 - 256 + wn + nt * 8 + 2 * t;
                float b0 = bias[cc] + proj_b[cc];
                float b1 = bias[cc + 1] + proj_b[cc + 1];
                float* A4 = acc[mt][nt];
                *(float2*)&out[(size_t)rowa * CDIM + cc] =
                    make_float2(A4[0] + b0, A4[1] + b1);
                *(float2*)&out[(size_t)(rowa + 8) * CDIM + cc] =
                    make_float2(A4[2] + b0, A4[3] + b1);
            }
        }
    }
}

// ---------------- kernel 2: per-row sparse softmax + aggregation ----------------
// (verbatim proven 140.5us version — s_cols SoA + s_p2 half array)
__global__ void __launch_bounds__(256)
attn_kernel(const float* __restrict__ adj, float* __restrict__ out) {
    __shared__ int     s_cols[MAXE];
    __shared__ __half2 s_p2[MAXE * 2];       // [e][4 heads as 2x half2]
    __shared__ float   s_part[8][32][9];     // [group][thread][8ch + pad]
    __shared__ float   s_red[NHEAD][8];
    __shared__ float   s_inv[NHEAD];
    __shared__ int     s_cnt;

    const int i = blockIdx.x;
    const int tid = threadIdx.x;
    const int lane = tid & 31;
    const int warp = tid >> 5;

    if (tid == 0) s_cnt = 0;
    __syncthreads();

    // ---- phase 1: gather nonzero columns (float4 reads, ballot compaction) ----
    const float4* arow = (const float4*)(adj + (size_t)i * NROWS);
    const unsigned ltmask = (1u << lane) - 1u;
    #pragma unroll
    for (int it = 0; it < 8; it++) {
        int idx4 = it * 256 + tid;
        float4 v = arow[idx4];
        bool n0 = v.x != 0.f, n1 = v.y != 0.f, n2 = v.z != 0.f, n3 = v.w != 0.f;
        unsigned b0 = __ballot_sync(0xFFFFFFFFu, n0);
        unsigned b1 = __ballot_sync(0xFFFFFFFFu, n1);
        unsigned b2 = __ballot_sync(0xFFFFFFFFu, n2);
        unsigned b3 = __ballot_sync(0xFFFFFFFFu, n3);
        int tot = __popc(b0) + __popc(b1) + __popc(b2) + __popc(b3);
        int base = 0;
        if (lane == 0 && tot) base = atomicAdd(&s_cnt, tot);
        base = __shfl_sync(0xFFFFFFFFu, base, 0);
        int c0 = idx4 * 4;
        int p0 = base + __popc(b0 & ltmask);
        int p1 = base + __popc(b0) + __popc(b1 & ltmask);
        int p2 = base + __popc(b0) + __popc(b1) + __popc(b2 & ltmask);
        int p3 = base + __popc(b0) + __popc(b1) + __popc(b2) + __popc(b3 & ltmask);
        if (n0 && p0 < MAXE) s_cols[p0] = c0;
        if (n1 && p1 < MAXE) s_cols[p1] = c0 + 1;
        if (n2 && p2 < MAXE) s_cols[p2] = c0 + 2;
        if (n3 && p3 < MAXE) s_cols[p3] = c0 + 3;
    }
    __syncthreads();
    const int cnt = min(s_cnt, MAXE);

    // ---- phase 2: lrelu + scaled exp, store half p, fp32 sums ----
    const float4 f2h = g_f2v[i];
    float Cx, Cy, Cz, Cw;
    {
        float gx = __int_as_float(g_maxf1i[0]);
        float gy = __int_as_float(g_maxf1i[1]);
        float gz = __int_as_float(g_maxf1i[2]);
        float gw = __int_as_float(g_maxf1i[3]);
        float ax = gx + f2h.x; ax = (ax > 0.f) ? ax : 0.2f * ax;
        float ay = gy + f2h.y; ay = (ay > 0.f) ? ay : 0.2f * ay;
        float az = gz + f2h.z; az = (az > 0.f) ? az : 0.2f * az;
        float aw = gw + f2h.w; aw = (aw > 0.f) ? aw : 0.2f * aw;
        Cx = LN256 - ax; Cy = LN256 - ay; Cz = LN256 - az; Cw = LN256 - aw;
    }
    float4 sm = make_float4(0.f, 0.f, 0.f, 0.f);
    for (int e = tid; e < cnt; e += 256) {
        int j = s_cols[e];
        float4 f1 = __ldg(&g_f1v[j]);
        float sx = f1.x + f2h.x; sx = (sx > 0.f) ? sx : 0.2f * sx;
        float sy = f1.y + f2h.y; sy = (sy > 0.f) ? sy : 0.2f * sy;
        float sz = f1.z + f2h.z; sz = (sz > 0.f) ? sz : 0.2f * sz;
        float sw = f1.w + f2h.w; sw = (sw > 0.f) ? sw : 0.2f * sw;
        float px = __expf(sx + Cx), py = __expf(sy + Cy);
        float pz = __expf(sz + Cz), pw = __expf(sw + Cw);
        s_p2[e * 2]     = __float22half2_rn(make_float2(px, py));
        s_p2[e * 2 + 1] = __float22half2_rn(make_float2(pz, pw));
        sm.x += px; sm.y += py; sm.z += pz; sm.w += pw;
    }
    #pragma unroll
    for (int off = 16; off; off >>= 1) {
        sm.x += __shfl_xor_sync(0xFFFFFFFFu, sm.x, off);
        sm.y += __shfl_xor_sync(0xFFFFFFFFu, sm.y, off);
        sm.z += __shfl_xor_sync(0xFFFFFFFFu, sm.z, off);
        sm.w += __shfl_xor_sync(0xFFFFFFFFu, sm.w, off);
    }
    if (lane == 0) {
        s_red[0][warp] = sm.x; s_red[1][warp] = sm.y;
        s_red[2][warp] = sm.z; s_red[3][warp] = sm.w;
    }
    __syncthreads();
    if (tid < NHEAD) {
        float D = 0.f;
        #pragma unroll
        for (int w = 0; w < 8; w++) D += s_red[tid][w];
        s_inv[tid] = (D > 0.f) ? (1.0f / D) : 0.f;
    }
    __syncthreads();

    // ---- phase 3: 8 edge-groups x 32 threads, HFMA2 on 8 fp16 channels ----
    const int g = warp;
    const int t = lane;
    const int h = t >> 3;
    const uint4* suph = (const uint4*)g_supp_h;
    const __half* sp = (const __half*)s_p2;

    float facc[8] = {};
    int e = g;
    for (; e + 56 < cnt; e += 64) {
        __half2 h0 = __float2half2_rn(0.f), h1 = h0, h2 = h0, h3 = h0;
        #pragma unroll
        for (int u = 0; u < 8; u++) {
            int ee = e + u * 8;
            int j = s_cols[ee];
            __half2 ph = __half2half2(sp[ee * 4 + h]);
            uint4 v = suph[(size_t)j * 32 + t];
            h0 = __hfma2(ph, *(__half2*)&v.x, h0);
            h1 = __hfma2(ph, *(__half2*)&v.y, h1);
            h2 = __hfma2(ph, *(__half2*)&v.z, h2);
            h3 = __hfma2(ph, *(__half2*)&v.w, h3);
        }
        float2 f0 = __half22float2(h0), f1 = __half22float2(h1);
        float2 f2 = __half22float2(h2), f3 = __half22float2(h3);
        facc[0] += f0.x; facc[1] += f0.y; facc[2] += f1.x; facc[3] += f1.y;
        facc[4] += f2.x; facc[5] += f2.y; facc[6] += f3.x; facc[7] += f3.y;
    }
    for (; e < cnt; e += 8) {
        int j = s_cols[e];
        float p = __half2float(sp[e * 4 + h]);
        uint4 v = suph[(size_t)j * 32 + t];
        float2 f0 = __half22float2(*(__half2*)&v.x);
        float2 f1 = __half22float2(*(__half2*)&v.y);
        float2 f2 = __half22float2(*(__half2*)&v.z);
        float2 f3 = __half22float2(*(__half2*)&v.w);
        facc[0] += p * f0.x; facc[1] += p * f0.y;
        facc[2] += p * f1.x; facc[3] += p * f1.y;
        facc[4] += p * f2.x; facc[5] += p * f2.y;
        facc[6] += p * f3.x; facc[7] += p * f3.y;
    }
    #pragma unroll
    for (int k = 0; k < 8; k++) s_part[g][t][k] = facc[k];
    __syncthreads();

    // ---- phase 4: combine 8 groups, normalize, add base, store ----
    if (tid < 32) {
        const float inv = s_inv[tid >> 3];
        float r[8] = {};
        #pragma unroll
        for (int gg = 0; gg < 8; gg++)
            #pragma unroll
            for (int k = 0; k < 8; k++)
                r[k] += s_part[gg][tid][k];
        float4* o = (float4*)(out + (size_t)i * CDIM);
        float4 b0 = o[tid * 2];
        float4 b1 = o[tid * 2 + 1];
        b0.x += r[0] * inv; b0.y += r[1] * inv; b0.z += r[2] * inv; b0.w += r[3] * inv;
        b1.x += r[4] * inv; b1.y += r[5] * inv; b1.z += r[6] * inv; b1.w += r[7] * inv;
        o[tid * 2]     = b0;
        o[tid * 2 + 1] = b1;
    }
}

// ---------------- launch ----------------
extern "C" void kernel_launch(void* const* d_in, const int* in_sizes, int n_in,
                              void* d_out, int out_size) {
    const float* inputs  = (const float*)d_in[0];  // [8192,256]
    const float* adj     = (const float*)d_in[1];  // [8192,8192]
    const float* weight  = (const float*)d_in[2];  // [256,256]
    const float* wu      = (const float*)d_in[3];  // [4,64,1]
    const float* wv      = (const float*)d_in[4];  // [4,64,1]
    const float* bias    = (const float*)d_in[5];  // [1,256]
    const float* proj_w  = (const float*)d_in[6];  // [256,256]
    const float* proj_b  = (const float*)d_in[7];  // [256]
    float* out = (float*)d_out;                    // [8192,256]

    split_a_kernel<<<(NROWS * KDIM / 4) / 256, 256>>>(inputs);
    pack_bt_kernel<<<NB, KDIM>>>(weight, proj_w);

    dim3 ggrid(NB / 64, NROWS / 128);
    gemm_kernel<<<ggrid, 256>>>(wu, wv, bias, proj_b, out);

    attn_kernel<<<NROWS, 256>>>(adj, out);
}